// round 2
// baseline (speedup 1.0000x reference)
#include <cuda_runtime.h>
#include <cuda_bf16.h>
#include <math.h>

// Problem dims (fixed by the dataset)
constexpr int BB = 8;      // batch
constexpr int SS = 2048;   // seq
constexpr int DD = 1024;   // model dim (= dk = dv)
constexpr int HH = 4096;   // mlp hidden

// ---------------- scratch (device globals; no allocations allowed) ----------
__device__ float g_h  [(size_t)BB*SS*DD];   // ln1(x)
__device__ float g_q  [(size_t)BB*SS*DD];
__device__ float g_k  [(size_t)BB*SS*DD];
__device__ float g_v  [(size_t)BB*SS*DD];
__device__ float g_s  [(size_t)BB*SS*SS];   // scores / softmax (in place)
__device__ float g_av [(size_t)BB*SS*DD];   // a @ v
__device__ float g_x2 [(size_t)BB*SS*DD];   // h + attn_out
__device__ float g_h2 [(size_t)BB*SS*DD];   // ln2(x2)
__device__ float g_ff [(size_t)BB*SS*HH];   // gelu(h2@w1+b1)

// ---------------- block reductions ------------------------------------------
__device__ __forceinline__ float blockReduceSum(float v, float* shm) {
    int lane = threadIdx.x & 31, wid = threadIdx.x >> 5;
    #pragma unroll
    for (int o = 16; o; o >>= 1) v += __shfl_xor_sync(0xffffffffu, v, o);
    if (lane == 0) shm[wid] = v;
    __syncthreads();
    if (wid == 0) {
        float x = (lane < (blockDim.x >> 5)) ? shm[lane] : 0.f;
        #pragma unroll
        for (int o = 16; o; o >>= 1) x += __shfl_xor_sync(0xffffffffu, x, o);
        if (lane == 0) shm[0] = x;
    }
    __syncthreads();
    float r = shm[0];
    __syncthreads();
    return r;
}

__device__ __forceinline__ float blockReduceMax(float v, float* shm) {
    int lane = threadIdx.x & 31, wid = threadIdx.x >> 5;
    #pragma unroll
    for (int o = 16; o; o >>= 1) v = fmaxf(v, __shfl_xor_sync(0xffffffffu, v, o));
    if (lane == 0) shm[wid] = v;
    __syncthreads();
    if (wid == 0) {
        float x = (lane < (blockDim.x >> 5)) ? shm[lane] : -INFINITY;
        #pragma unroll
        for (int o = 16; o; o >>= 1) x = fmaxf(x, __shfl_xor_sync(0xffffffffu, x, o));
        if (lane == 0) shm[0] = x;
    }
    __syncthreads();
    float r = shm[0];
    __syncthreads();
    return r;
}

// ---------------- LayerNorm: one block per row of D=1024 --------------------
__global__ void __launch_bounds__(256) ln_kernel(const float* __restrict__ x,
                                                 const float* __restrict__ g,
                                                 const float* __restrict__ b,
                                                 float* __restrict__ y) {
    __shared__ float shm[32];
    long long row = blockIdx.x;
    const float* px = x + row * DD;
    float*       py = y + row * DD;
    int t = threadIdx.x;                       // 256 threads, 4 elems each
    float4 v = *reinterpret_cast<const float4*>(px + t * 4);
    float s  = v.x + v.y + v.z + v.w;
    float sq = v.x*v.x + v.y*v.y + v.z*v.z + v.w*v.w;
    float total  = blockReduceSum(s,  shm);
    float total2 = blockReduceSum(sq, shm);
    float mean = total * (1.0f / DD);
    float var  = total2 * (1.0f / DD) - mean * mean;
    float rstd = rsqrtf(var + 1e-5f);
    float4 gg = *reinterpret_cast<const float4*>(g + t * 4);
    float4 bb = *reinterpret_cast<const float4*>(b + t * 4);
    float4 o;
    o.x = (v.x - mean) * rstd * gg.x + bb.x;
    o.y = (v.y - mean) * rstd * gg.y + bb.y;
    o.z = (v.z - mean) * rstd * gg.z + bb.z;
    o.w = (v.w - mean) * rstd * gg.w + bb.w;
    *reinterpret_cast<float4*>(py + t * 4) = o;
}

// ---------------- Softmax: one block per row of S=2048 ----------------------
__global__ void __launch_bounds__(256) softmax_kernel(float* __restrict__ s) {
    __shared__ float shm[32];
    long long row = blockIdx.x;
    float* p = s + row * SS;
    int t = threadIdx.x;
    float v[8];
    float mx = -INFINITY;
    #pragma unroll
    for (int i = 0; i < 8; i++) { v[i] = p[t + i * 256]; mx = fmaxf(mx, v[i]); }
    mx = blockReduceMax(mx, shm);
    float sum = 0.f;
    #pragma unroll
    for (int i = 0; i < 8; i++) { v[i] = expf(v[i] - mx); sum += v[i]; }
    sum = blockReduceSum(sum, shm);
    float inv = 1.0f / sum;
    #pragma unroll
    for (int i = 0; i < 8; i++) p[t + i * 256] = v[i] * inv;
}

// ---------------- SGEMM 128x128x16, 8x8 microtile, fused epilogue -----------
// C[M,N] = alpha * A[M,K] @ op(B) (+bias) (gelu?) (+resid), row-major.
// TRANS_B=false: B is [K,N]. TRANS_B=true: B is [N,K] (C = A @ B^T).
// All of M, N multiples of 128; K multiple of 16 (true for every call here).
template <bool TRANS_B>
__global__ void __launch_bounds__(256) gemm128(
    const float* __restrict__ A, const float* __restrict__ Bm, float* __restrict__ C,
    int M, int N, int K,
    long long sA, long long sB, long long sC,
    float alpha, const float* __restrict__ bias,
    const float* __restrict__ resid, long long sR, int act)
{
    __shared__ float As[16][128];
    __shared__ float Bs[16][128];
    const int bz = blockIdx.z;
    const float* Ab = A  + (long long)bz * sA;
    const float* Bb = Bm + (long long)bz * sB;
    float*       Cb = C  + (long long)bz * sC;
    const int n0 = blockIdx.x * 128;
    const int m0 = blockIdx.y * 128;
    const int tid = threadIdx.x;
    const int tr = tid >> 4, tc = tid & 15;

    float acc[8][8];
    #pragma unroll
    for (int i = 0; i < 8; i++)
        #pragma unroll
        for (int j = 0; j < 8; j++) acc[i][j] = 0.f;

    for (int k0 = 0; k0 < K; k0 += 16) {
        // stage A tile (transposed into smem: As[k][m])
        #pragma unroll
        for (int tph = 0; tph < 2; tph++) {
            int id = tid + tph * 256;
            int m  = id >> 2;
            int kq = (id & 3) * 4;
            float4 a4 = *reinterpret_cast<const float4*>(Ab + (long long)(m0 + m) * K + k0 + kq);
            As[kq + 0][m] = a4.x; As[kq + 1][m] = a4.y;
            As[kq + 2][m] = a4.z; As[kq + 3][m] = a4.w;
        }
        // stage B tile (Bs[k][n])
        if (!TRANS_B) {
            #pragma unroll
            for (int tph = 0; tph < 2; tph++) {
                int id = tid + tph * 256;
                int kk = id >> 5;
                int n4 = (id & 31) * 4;
                float4 b4 = *reinterpret_cast<const float4*>(Bb + (long long)(k0 + kk) * N + n0 + n4);
                *reinterpret_cast<float4*>(&Bs[kk][n4]) = b4;
            }
        } else {
            #pragma unroll
            for (int tph = 0; tph < 2; tph++) {
                int id = tid + tph * 256;
                int n  = id >> 2;
                int kq = (id & 3) * 4;
                float4 b4 = *reinterpret_cast<const float4*>(Bb + (long long)(n0 + n) * K + k0 + kq);
                Bs[kq + 0][n] = b4.x; Bs[kq + 1][n] = b4.y;
                Bs[kq + 2][n] = b4.z; Bs[kq + 3][n] = b4.w;
            }
        }
        __syncthreads();

        #pragma unroll
        for (int kk = 0; kk < 16; kk++) {
            float a[8], b[8];
            #pragma unroll
            for (int i = 0; i < 8; i++) a[i] = As[kk][tr * 8 + i];
            #pragma unroll
            for (int j = 0; j < 8; j++) b[j] = Bs[kk][tc * 8 + j];
            #pragma unroll
            for (int i = 0; i < 8; i++)
                #pragma unroll
                for (int j = 0; j < 8; j++)
                    acc[i][j] = fmaf(a[i], b[j], acc[i][j]);
        }
        __syncthreads();
    }

    // epilogue: alpha, +bias, gelu, +resid
    #pragma unroll
    for (int i = 0; i < 8; i++) {
        int m = m0 + tr * 8 + i;
        #pragma unroll
        for (int j = 0; j < 8; j++) {
            int n = n0 + tc * 8 + j;
            float c = acc[i][j] * alpha;
            if (bias)  c += __ldg(bias + n);
            if (act == 1) c = 0.5f * c * (1.0f + erff(c * 0.70710678118654752f));
            if (resid) c += resid[(long long)bz * sR + (long long)m * N + n];
            Cb[(long long)m * N + n] = c;
        }
    }
}

// ---------------- driver -----------------------------------------------------
static inline float* sym(const void* s) {
    void* p = nullptr;
    cudaGetSymbolAddress(&p, s);
    return reinterpret_cast<float*>(p);
}

extern "C" void kernel_launch(void* const* d_in, const int* in_sizes, int n_in,
                              void* d_out, int out_size) {
    const float* x     = (const float*)d_in[0];
    const float* ln1_g = (const float*)d_in[1];
    const float* ln1_b = (const float*)d_in[2];
    const float* wq    = (const float*)d_in[3];
    const float* wk    = (const float*)d_in[4];
    const float* wv    = (const float*)d_in[5];
    const float* wo    = (const float*)d_in[6];
    const float* ln2_g = (const float*)d_in[7];
    const float* ln2_b = (const float*)d_in[8];
    const float* w1    = (const float*)d_in[9];
    const float* b1    = (const float*)d_in[10];
    const float* w2    = (const float*)d_in[11];
    const float* b2    = (const float*)d_in[12];
    float* out = (float*)d_out;

    float* h  = sym(g_h);
    float* q  = sym(g_q);
    float* k  = sym(g_k);
    float* v  = sym(g_v);
    float* s  = sym(g_s);
    float* av = sym(g_av);
    float* x2 = sym(g_x2);
    float* h2 = sym(g_h2);
    float* ff = sym(g_ff);

    const int rows = BB * SS;                 // 16384
    const float scale = 1.0f / sqrtf((float)DD);

    // 1) h = ln1(x)
    ln_kernel<<<rows, 256>>>(x, ln1_g, ln1_b, h);

    // 2-4) q,k,v = h @ w{q,k,v}   [16384,1024]@[1024,1024]
    {
        dim3 grid(DD / 128, rows / 128, 1);
        gemm128<false><<<grid, 256>>>(h, wq, q, rows, DD, DD, 0, 0, 0, 1.f, nullptr, nullptr, 0, 0);
        gemm128<false><<<grid, 256>>>(h, wk, k, rows, DD, DD, 0, 0, 0, 1.f, nullptr, nullptr, 0, 0);
        gemm128<false><<<grid, 256>>>(h, wv, v, rows, DD, DD, 0, 0, 0, 1.f, nullptr, nullptr, 0, 0);
    }

    // 5) s = scale * q @ k^T  (batched NT, per-batch 2048x2048x1024)
    {
        dim3 grid(SS / 128, SS / 128, BB);
        gemm128<true><<<grid, 256>>>(q, k, s, SS, SS, DD,
                                     (long long)SS * DD, (long long)SS * DD, (long long)SS * SS,
                                     scale, nullptr, nullptr, 0, 0);
    }

    // 6) softmax rows (in place)
    softmax_kernel<<<BB * SS, 256>>>(s);

    // 7) av = a @ v  (batched NN, 2048x1024x2048)
    {
        dim3 grid(DD / 128, SS / 128, BB);
        gemm128<false><<<grid, 256>>>(s, v, av, SS, DD, SS,
                                      (long long)SS * SS, (long long)SS * DD, (long long)SS * DD,
                                      1.f, nullptr, nullptr, 0, 0);
    }

    // 8) x2 = h + av @ wo   (residual fused)
    {
        dim3 grid(DD / 128, rows / 128, 1);
        gemm128<false><<<grid, 256>>>(av, wo, x2, rows, DD, DD, 0, 0, 0,
                                      1.f, nullptr, h, 0, 0);
    }

    // 9) h2 = ln2(x2)
    ln_kernel<<<rows, 256>>>(x2, ln2_g, ln2_b, h2);

    // 10) ff = gelu(h2 @ w1 + b1)   [16384,1024]@[1024,4096]
    {
        dim3 grid(HH / 128, rows / 128, 1);
        gemm128<false><<<grid, 256>>>(h2, w1, ff, rows, HH, DD, 0, 0, 0,
                                      1.f, b1, nullptr, 0, 1);
    }

    // 11) out = x2 + ff @ w2 + b2   [16384,4096]@[4096,1024]
    {
        dim3 grid(DD / 128, rows / 128, 1);
        gemm128<false><<<grid, 256>>>(ff, w2, out, rows, DD, HH, 0, 0, 0,
                                      1.f, b2, x2, 0, 0);
    }
}

// round 15
// speedup vs baseline: 2.5978x; 2.5978x over previous
#include <cuda_runtime.h>
#include <cuda_bf16.h>
#include <math.h>
#include <stdint.h>

constexpr int BB = 8, SS = 2048, DD = 1024, HH = 4096;

// ---------------- scratch ----------------------------------------------------
__device__ float g_h  [(size_t)BB*SS*DD];
__device__ float g_v  [(size_t)BB*SS*DD];
__device__ float g_s  [(size_t)BB*SS*SS];
__device__ float g_x2 [(size_t)BB*SS*DD];
__device__ __nv_bfloat16 g_h_hi [(size_t)BB*SS*DD],  g_h_lo [(size_t)BB*SS*DD];
__device__ __nv_bfloat16 g_q_hi [(size_t)BB*SS*DD],  g_q_lo [(size_t)BB*SS*DD];
__device__ __nv_bfloat16 g_k_hi [(size_t)BB*SS*DD],  g_k_lo [(size_t)BB*SS*DD];
__device__ __nv_bfloat16 g_vt_hi[(size_t)BB*SS*DD],  g_vt_lo[(size_t)BB*SS*DD];
__device__ __nv_bfloat16 g_s_hi [(size_t)BB*SS*SS],  g_s_lo [(size_t)BB*SS*SS];
__device__ __nv_bfloat16 g_av_hi[(size_t)BB*SS*DD],  g_av_lo[(size_t)BB*SS*DD];
__device__ __nv_bfloat16 g_h2_hi[(size_t)BB*SS*DD],  g_h2_lo[(size_t)BB*SS*DD];
__device__ __nv_bfloat16 g_ff_hi[(size_t)BB*SS*HH],  g_ff_lo[(size_t)BB*SS*HH];
__device__ __nv_bfloat16 g_wqt_hi[(size_t)DD*DD], g_wqt_lo[(size_t)DD*DD];
__device__ __nv_bfloat16 g_wkt_hi[(size_t)DD*DD], g_wkt_lo[(size_t)DD*DD];
__device__ __nv_bfloat16 g_wvt_hi[(size_t)DD*DD], g_wvt_lo[(size_t)DD*DD];
__device__ __nv_bfloat16 g_wot_hi[(size_t)DD*DD], g_wot_lo[(size_t)DD*DD];
__device__ __nv_bfloat16 g_w1t_hi[(size_t)DD*HH], g_w1t_lo[(size_t)DD*HH];
__device__ __nv_bfloat16 g_w2t_hi[(size_t)DD*HH], g_w2t_lo[(size_t)DD*HH];

// ---------------- helpers ----------------------------------------------------
__device__ __forceinline__ void hilo(float v, float& hf, float& lf) {
    __nv_bfloat16 h = __float2bfloat16(v);
    hf = __bfloat162float(h);
    lf = v - hf;
}
__device__ __forceinline__ uint32_t pack_bf2(float a, float b) {
    __nv_bfloat162 t = __floats2bfloat162_rn(a, b);
    return *reinterpret_cast<uint32_t*>(&t);
}
__device__ __forceinline__ uint32_t smem_u32(const void* p) {
    uint32_t a;
    asm("{ .reg .u64 t; cvta.to.shared.u64 t, %1; cvt.u32.u64 %0, t; }" : "=r"(a) : "l"(p));
    return a;
}
__device__ __forceinline__ void ldsm_x4(uint32_t* r, uint32_t addr) {
    asm volatile("ldmatrix.sync.aligned.m8n8.x4.shared.b16 {%0,%1,%2,%3}, [%4];"
                 : "=r"(r[0]), "=r"(r[1]), "=r"(r[2]), "=r"(r[3]) : "r"(addr));
}
__device__ __forceinline__ void ldsm_x2(uint32_t* r, uint32_t addr) {
    asm volatile("ldmatrix.sync.aligned.m8n8.x2.shared.b16 {%0,%1}, [%2];"
                 : "=r"(r[0]), "=r"(r[1]) : "r"(addr));
}
__device__ __forceinline__ void mma16816(float* d, const uint32_t* a, const uint32_t* b) {
    asm volatile("mma.sync.aligned.m16n8k16.row.col.f32.bf16.bf16.f32 "
                 "{%0,%1,%2,%3},{%4,%5,%6,%7},{%8,%9},{%0,%1,%2,%3};"
                 : "+f"(d[0]), "+f"(d[1]), "+f"(d[2]), "+f"(d[3])
                 : "r"(a[0]), "r"(a[1]), "r"(a[2]), "r"(a[3]), "r"(b[0]), "r"(b[1]));
}

// ---------------- block reductions -------------------------------------------
__device__ __forceinline__ float blockReduceSum(float v, float* shm) {
    int lane = threadIdx.x & 31, wid = threadIdx.x >> 5;
    #pragma unroll
    for (int o = 16; o; o >>= 1) v += __shfl_xor_sync(0xffffffffu, v, o);
    if (lane == 0) shm[wid] = v;
    __syncthreads();
    if (wid == 0) {
        float x = (lane < (blockDim.x >> 5)) ? shm[lane] : 0.f;
        #pragma unroll
        for (int o = 16; o; o >>= 1) x += __shfl_xor_sync(0xffffffffu, x, o);
        if (lane == 0) shm[0] = x;
    }
    __syncthreads();
    float r = shm[0]; __syncthreads(); return r;
}
__device__ __forceinline__ float blockReduceMax(float v, float* shm) {
    int lane = threadIdx.x & 31, wid = threadIdx.x >> 5;
    #pragma unroll
    for (int o = 16; o; o >>= 1) v = fmaxf(v, __shfl_xor_sync(0xffffffffu, v, o));
    if (lane == 0) shm[wid] = v;
    __syncthreads();
    if (wid == 0) {
        float x = (lane < (blockDim.x >> 5)) ? shm[lane] : -INFINITY;
        #pragma unroll
        for (int o = 16; o; o >>= 1) x = fmaxf(x, __shfl_xor_sync(0xffffffffu, x, o));
        if (lane == 0) shm[0] = x;
    }
    __syncthreads();
    float r = shm[0]; __syncthreads(); return r;
}

// ---------------- LayerNorm (fp32 + hi/lo outputs) ---------------------------
__global__ void __launch_bounds__(256) ln_kernel(
    const float* __restrict__ x, const float* __restrict__ g, const float* __restrict__ b,
    float* __restrict__ outF, __nv_bfloat16* __restrict__ outHi, __nv_bfloat16* __restrict__ outLo)
{
    __shared__ float shm[32];
    long long row = blockIdx.x;
    const float* px = x + row * DD;
    int t = threadIdx.x;
    float4 v = *reinterpret_cast<const float4*>(px + t * 4);
    float s  = v.x + v.y + v.z + v.w;
    float sq = v.x*v.x + v.y*v.y + v.z*v.z + v.w*v.w;
    float total  = blockReduceSum(s,  shm);
    float total2 = blockReduceSum(sq, shm);
    float mean = total * (1.0f / DD);
    float var  = total2 * (1.0f / DD) - mean * mean;
    float rstd = rsqrtf(var + 1e-5f);
    float4 gg = *reinterpret_cast<const float4*>(g + t * 4);
    float4 bb = *reinterpret_cast<const float4*>(b + t * 4);
    float4 o;
    o.x = (v.x - mean) * rstd * gg.x + bb.x;
    o.y = (v.y - mean) * rstd * gg.y + bb.y;
    o.z = (v.z - mean) * rstd * gg.z + bb.z;
    o.w = (v.w - mean) * rstd * gg.w + bb.w;
    long long off = row * DD + t * 4;
    if (outF) *reinterpret_cast<float4*>(outF + off) = o;
    float h0,h1,h2,h3,l0,l1,l2,l3;
    hilo(o.x,h0,l0); hilo(o.y,h1,l1); hilo(o.z,h2,l2); hilo(o.w,h3,l3);
    uint2 uh; uh.x = pack_bf2(h0,h1); uh.y = pack_bf2(h2,h3);
    uint2 ul; ul.x = pack_bf2(l0,l1); ul.y = pack_bf2(l2,l3);
    *reinterpret_cast<uint2*>(outHi + off) = uh;
    *reinterpret_cast<uint2*>(outLo + off) = ul;
}

// ---------------- Softmax (fp32 in, hi/lo out) -------------------------------
__global__ void __launch_bounds__(256) softmax_kernel(
    const float* __restrict__ s, __nv_bfloat16* __restrict__ oHi, __nv_bfloat16* __restrict__ oLo)
{
    __shared__ float shm[32];
    long long row = blockIdx.x;
    const float* p = s + row * SS;
    int t = threadIdx.x;
    float v[8];
    float mx = -INFINITY;
    #pragma unroll
    for (int i = 0; i < 8; i++) { v[i] = p[t + i * 256]; mx = fmaxf(mx, v[i]); }
    mx = blockReduceMax(mx, shm);
    float sum = 0.f;
    #pragma unroll
    for (int i = 0; i < 8; i++) { v[i] = expf(v[i] - mx); sum += v[i]; }
    sum = blockReduceSum(sum, shm);
    float inv = 1.0f / sum;
    #pragma unroll
    for (int i = 0; i < 8; i++) {
        float val = v[i] * inv, hf, lf;
        hilo(val, hf, lf);
        long long off = row * SS + t + i * 256;
        oHi[off] = __float2bfloat16(hf);
        oLo[off] = __float2bfloat16(lf);
    }
}

// ---------------- transpose-convert: in[R,C] fp32 -> out[C,R] hi/lo bf16 -----
__global__ void __launch_bounds__(256) transconv(
    const float* __restrict__ in, __nv_bfloat16* __restrict__ ohi, __nv_bfloat16* __restrict__ olo,
    int R, int C, long long sIn, long long sOut)
{
    __shared__ float t[32][33];
    const float* I = in + (long long)blockIdx.z * sIn;
    int c0 = blockIdx.x * 32, r0 = blockIdx.y * 32;
    int tx = threadIdx.x, ty = threadIdx.y;
    #pragma unroll
    for (int i = ty; i < 32; i += 8)
        t[i][tx] = I[(long long)(r0 + i) * C + c0 + tx];
    __syncthreads();
    long long ob = (long long)blockIdx.z * sOut;
    #pragma unroll
    for (int i = ty; i < 32; i += 8) {
        float v = t[tx][i];           // = in[r0+tx][c0+i]
        float hf, lf; hilo(v, hf, lf);
        long long off = ob + (long long)(c0 + i) * R + r0 + tx;
        ohi[off] = __float2bfloat16(hf);
        olo[off] = __float2bfloat16(lf);
    }
}

// ---------------- bf16x3 HMMA GEMM (mma.sync, sm_80 PTX path) ----------------
// C[M,N] = alpha * A[M,K] @ B[N,K]^T, A/B as bf16 hi/lo pairs.
// Tile 128x128, k-chunk 64, 8 warps (2x4), warp tile 64x32, 3 compensated passes.
constexpr int ROWB   = 144;               // 64 bf16 = 128B + 16B pad (conflict-free ldmatrix)
constexpr int TILEB  = 128 * ROWB;        // 18432 B per tile
constexpr int STAGEB = 4 * TILEB;         // Ahi, Alo, Bhi, Blo = 73728 B
constexpr int SMEMB  = 2 * STAGEB;        // 147456 B

__global__ void __launch_bounds__(256) gemm_tc(
    const __nv_bfloat16* __restrict__ Ahi, const __nv_bfloat16* __restrict__ Alo,
    const __nv_bfloat16* __restrict__ Bhi, const __nv_bfloat16* __restrict__ Blo,
    float* __restrict__ outF, __nv_bfloat16* __restrict__ outHi, __nv_bfloat16* __restrict__ outLo,
    int N, int K,
    long long sA, long long sB, long long sC,
    float alpha, const float* __restrict__ bias,
    const float* __restrict__ resid, long long sR, int act)
{
    extern __shared__ __align__(16) char smem[];
    uint32_t sb = smem_u32(smem);
    const int tid = threadIdx.x, wid = tid >> 5, lane = tid & 31;
    const long long bz = blockIdx.z;
    const int n0 = blockIdx.x << 7, m0 = blockIdx.y << 7;
    const int m0w = (wid >> 2) << 6;      // warp row offset (0 or 64)
    const int n0w = (wid & 3) << 5;       // warp col offset (0,32,64,96)

    const __nv_bfloat16* base[4];
    base[0] = Ahi + bz * sA + (long long)m0 * K;
    base[1] = Alo + bz * sA + (long long)m0 * K;
    base[2] = Bhi + bz * sB + (long long)n0 * K;
    base[3] = Blo + bz * sB + (long long)n0 * K;

    const int NC = K >> 6;

    // loader: 4 tiles x (128 rows x 8 segs of 16B); dest row stride 144B
    auto load_chunk = [&](uint32_t stg, int k0) {
        #pragma unroll
        for (int t4 = 0; t4 < 4; t4++) {
            const __nv_bfloat16* gb = base[t4] + k0;
            #pragma unroll
            for (int ii = 0; ii < 4; ii++) {
                int task = ii * 256 + tid;       // 0..1023
                int r = task >> 3, seg = task & 7;
                const __nv_bfloat16* g = gb + (long long)r * K + seg * 8;
                uint32_t d = stg + t4 * TILEB + r * ROWB + seg * 16;
                asm volatile("cp.async.cg.shared.global [%0], [%1], 16;" :: "r"(d), "l"(g) : "memory");
            }
        }
    };

    float acc[4][4][4];
    #pragma unroll
    for (int mt = 0; mt < 4; mt++)
        #pragma unroll
        for (int nt = 0; nt < 4; nt++)
            #pragma unroll
            for (int i = 0; i < 4; i++) acc[mt][nt][i] = 0.f;

    load_chunk(sb, 0);
    asm volatile("cp.async.commit_group;" ::: "memory");

    for (int c = 0; c < NC; c++) {
        if (c + 1 < NC) {
            load_chunk(sb + (((c + 1) & 1) ? STAGEB : 0), (c + 1) << 6);
            asm volatile("cp.async.commit_group;" ::: "memory");
            asm volatile("cp.async.wait_group 1;" ::: "memory");
        } else {
            asm volatile("cp.async.wait_group 0;" ::: "memory");
        }
        __syncthreads();

        const uint32_t stg = sb + ((c & 1) ? STAGEB : 0);
        const uint32_t aHiB = stg, aLoB = stg + TILEB, bHiB = stg + 2*TILEB, bLoB = stg + 3*TILEB;
        // per-lane ldmatrix address components
        const uint32_t aRow = (m0w + (lane & 15)) * ROWB + ((lane >> 4) << 3) * 2;
        const uint32_t bRow = (n0w + (lane & 7)) * ROWB + (((lane >> 3) & 1) << 3) * 2;

        #pragma unroll
        for (int ks = 0; ks < 4; ks++) {
            const uint32_t kOff = (ks << 4) * 2;   // ks*16 bf16 = 32B
            uint32_t ah[4][4], bh[4][2], bl[4][2];
            #pragma unroll
            for (int mt = 0; mt < 4; mt++) ldsm_x4(ah[mt], aHiB + aRow + (mt << 4) * ROWB + kOff);
            #pragma unroll
            for (int nt = 0; nt < 4; nt++) ldsm_x2(bh[nt], bHiB + bRow + (nt << 3) * ROWB + kOff);
            #pragma unroll
            for (int nt = 0; nt < 4; nt++) ldsm_x2(bl[nt], bLoB + bRow + (nt << 3) * ROWB + kOff);
            #pragma unroll
            for (int mt = 0; mt < 4; mt++)
                #pragma unroll
                for (int nt = 0; nt < 4; nt++) mma16816(acc[mt][nt], ah[mt], bh[nt]);
            #pragma unroll
            for (int mt = 0; mt < 4; mt++)
                #pragma unroll
                for (int nt = 0; nt < 4; nt++) mma16816(acc[mt][nt], ah[mt], bl[nt]);
            uint32_t al[4][4];
            #pragma unroll
            for (int mt = 0; mt < 4; mt++) ldsm_x4(al[mt], aLoB + aRow + (mt << 4) * ROWB + kOff);
            #pragma unroll
            for (int mt = 0; mt < 4; mt++)
                #pragma unroll
                for (int nt = 0; nt < 4; nt++) mma16816(acc[mt][nt], al[mt], bh[nt]);
        }
        __syncthreads();   // all warps done with this buffer before it is reloaded
    }

    // epilogue: acc -> smem [128][132] -> coalesced global with fused ops
    float* epi = reinterpret_cast<float*>(smem);
    #pragma unroll
    for (int mt = 0; mt < 4; mt++)
        #pragma unroll
        for (int nt = 0; nt < 4; nt++) {
            int r = m0w + (mt << 4) + (lane >> 2);
            int cc = n0w + (nt << 3) + ((lane & 3) << 1);
            epi[r * 132 + cc]           = acc[mt][nt][0];
            epi[r * 132 + cc + 1]       = acc[mt][nt][1];
            epi[(r + 8) * 132 + cc]     = acc[mt][nt][2];
            epi[(r + 8) * 132 + cc + 1] = acc[mt][nt][3];
        }
    __syncthreads();

    #pragma unroll
    for (int i = 0; i < 16; i++) {
        int f = i * 256 + tid;          // float4 index within 128x128 tile
        int mm = f >> 5, q4 = (f & 31) << 2;
        float4 v = *reinterpret_cast<float4*>(&epi[mm * 132 + q4]);
        v.x *= alpha; v.y *= alpha; v.z *= alpha; v.w *= alpha;
        if (bias) {
            float4 bb = *reinterpret_cast<const float4*>(bias + n0 + q4);
            v.x += bb.x; v.y += bb.y; v.z += bb.z; v.w += bb.w;
        }
        if (act == 1) {
            v.x = 0.5f * v.x * (1.0f + erff(v.x * 0.70710678118654752f));
            v.y = 0.5f * v.y * (1.0f + erff(v.y * 0.70710678118654752f));
            v.z = 0.5f * v.z * (1.0f + erff(v.z * 0.70710678118654752f));
            v.w = 0.5f * v.w * (1.0f + erff(v.w * 0.70710678118654752f));
        }
        long long goff = bz * sC + (long long)(m0 + mm) * N + n0 + q4;
        if (resid) {
            float4 rr = *reinterpret_cast<const float4*>(resid + bz * sR + (long long)(m0 + mm) * N + n0 + q4);
            v.x += rr.x; v.y += rr.y; v.z += rr.z; v.w += rr.w;
        }
        if (outF) *reinterpret_cast<float4*>(outF + goff) = v;
        if (outHi) {
            float h0,h1,h2,h3,l0,l1,l2,l3;
            hilo(v.x,h0,l0); hilo(v.y,h1,l1); hilo(v.z,h2,l2); hilo(v.w,h3,l3);
            uint2 uh; uh.x = pack_bf2(h0,h1); uh.y = pack_bf2(h2,h3);
            uint2 ul; ul.x = pack_bf2(l0,l1); ul.y = pack_bf2(l2,l3);
            *reinterpret_cast<uint2*>(outHi + goff) = uh;
            *reinterpret_cast<uint2*>(outLo + goff) = ul;
        }
    }
}

// ---------------- driver -----------------------------------------------------
template <typename T>
static inline T* sym(const void* s) {
    void* p = nullptr;
    cudaGetSymbolAddress(&p, s);
    return reinterpret_cast<T*>(p);
}

extern "C" void kernel_launch(void* const* d_in, const int* in_sizes, int n_in,
                              void* d_out, int out_size) {
    const float* x     = (const float*)d_in[0];
    const float* ln1_g = (const float*)d_in[1];
    const float* ln1_b = (const float*)d_in[2];
    const float* wq    = (const float*)d_in[3];
    const float* wk    = (const float*)d_in[4];
    const float* wv    = (const float*)d_in[5];
    const float* wo    = (const float*)d_in[6];
    const float* ln2_g = (const float*)d_in[7];
    const float* ln2_b = (const float*)d_in[8];
    const float* w1    = (const float*)d_in[9];
    const float* b1    = (const float*)d_in[10];
    const float* w2    = (const float*)d_in[11];
    const float* b2    = (const float*)d_in[12];
    float* out = (float*)d_out;

    float* h   = sym<float>(g_h);
    float* v   = sym<float>(g_v);
    float* s   = sym<float>(g_s);
    float* x2  = sym<float>(g_x2);
    __nv_bfloat16 *hHi = sym<__nv_bfloat16>(g_h_hi),  *hLo = sym<__nv_bfloat16>(g_h_lo);
    __nv_bfloat16 *qHi = sym<__nv_bfloat16>(g_q_hi),  *qLo = sym<__nv_bfloat16>(g_q_lo);
    __nv_bfloat16 *kHi = sym<__nv_bfloat16>(g_k_hi),  *kLo = sym<__nv_bfloat16>(g_k_lo);
    __nv_bfloat16 *vtHi= sym<__nv_bfloat16>(g_vt_hi), *vtLo= sym<__nv_bfloat16>(g_vt_lo);
    __nv_bfloat16 *sHi = sym<__nv_bfloat16>(g_s_hi),  *sLo = sym<__nv_bfloat16>(g_s_lo);
    __nv_bfloat16 *avHi= sym<__nv_bfloat16>(g_av_hi), *avLo= sym<__nv_bfloat16>(g_av_lo);
    __nv_bfloat16 *h2Hi= sym<__nv_bfloat16>(g_h2_hi), *h2Lo= sym<__nv_bfloat16>(g_h2_lo);
    __nv_bfloat16 *ffHi= sym<__nv_bfloat16>(g_ff_hi), *ffLo= sym<__nv_bfloat16>(g_ff_lo);
    __nv_bfloat16 *wqtH= sym<__nv_bfloat16>(g_wqt_hi),*wqtL= sym<__nv_bfloat16>(g_wqt_lo);
    __nv_bfloat16 *wktH= sym<__nv_bfloat16>(g_wkt_hi),*wktL= sym<__nv_bfloat16>(g_wkt_lo);
    __nv_bfloat16 *wvtH= sym<__nv_bfloat16>(g_wvt_hi),*wvtL= sym<__nv_bfloat16>(g_wvt_lo);
    __nv_bfloat16 *wotH= sym<__nv_bfloat16>(g_wot_hi),*wotL= sym<__nv_bfloat16>(g_wot_lo);
    __nv_bfloat16 *w1tH= sym<__nv_bfloat16>(g_w1t_hi),*w1tL= sym<__nv_bfloat16>(g_w1t_lo);
    __nv_bfloat16 *w2tH= sym<__nv_bfloat16>(g_w2t_hi),*w2tL= sym<__nv_bfloat16>(g_w2t_lo);

    cudaFuncSetAttribute(gemm_tc, cudaFuncAttributeMaxDynamicSharedMemorySize, SMEMB);
    const int SM = SMEMB;
    const int rows = BB * SS;
    const float scale = 1.0f / sqrtf((float)DD);
    const long long SD = (long long)SS * DD, SSq = (long long)SS * SS;

    // 1) h = ln1(x): fp32 + hi/lo
    ln_kernel<<<rows, 256>>>(x, ln1_g, ln1_b, h, hHi, hLo);

    // 2) weight transposes -> [N,K] hi/lo
    {
        dim3 b(32, 8);
        transconv<<<dim3(32, 32, 1), b>>>(wq, wqtH, wqtL, DD, DD, 0, 0);
        transconv<<<dim3(32, 32, 1), b>>>(wk, wktH, wktL, DD, DD, 0, 0);
        transconv<<<dim3(32, 32, 1), b>>>(wv, wvtH, wvtL, DD, DD, 0, 0);
        transconv<<<dim3(32, 32, 1), b>>>(wo, wotH, wotL, DD, DD, 0, 0);
        transconv<<<dim3(128, 32, 1), b>>>(w1, w1tH, w1tL, DD, HH, 0, 0);  // [1024,4096] -> [4096,1024]
        transconv<<<dim3(32, 128, 1), b>>>(w2, w2tH, w2tL, HH, DD, 0, 0);  // [4096,1024] -> [1024,4096]
    }

    // 3) q,k (hi/lo out), v (fp32 out)
    {
        dim3 grid(DD / 128, rows / 128, 1);
        gemm_tc<<<grid, 256, SM>>>(hHi, hLo, wqtH, wqtL, nullptr, qHi, qLo, DD, DD, 0, 0, 0, 1.f, nullptr, nullptr, 0, 0);
        gemm_tc<<<grid, 256, SM>>>(hHi, hLo, wktH, wktL, nullptr, kHi, kLo, DD, DD, 0, 0, 0, 1.f, nullptr, nullptr, 0, 0);
        gemm_tc<<<grid, 256, SM>>>(hHi, hLo, wvtH, wvtL, v, nullptr, nullptr, DD, DD, 0, 0, 0, 1.f, nullptr, nullptr, 0, 0);
    }

    // 4) v^T per batch -> [D,S] hi/lo
    transconv<<<dim3(DD / 32, SS / 32, BB), dim3(32, 8)>>>(v, vtHi, vtLo, SS, DD, SD, SD);

    // 5) s = scale * q @ k^T   (batched)
    gemm_tc<<<dim3(SS / 128, SS / 128, BB), 256, SM>>>(qHi, qLo, kHi, kLo, s, nullptr, nullptr,
                                                       SS, DD, SD, SD, SSq, scale, nullptr, nullptr, 0, 0);

    // 6) softmax -> hi/lo
    softmax_kernel<<<rows, 256>>>(s, sHi, sLo);

    // 7) av = a @ v   (B = v^T [D,S], batched)
    gemm_tc<<<dim3(DD / 128, SS / 128, BB), 256, SM>>>(sHi, sLo, vtHi, vtLo, nullptr, avHi, avLo,
                                                       DD, SS, SSq, SD, SD, 1.f, nullptr, nullptr, 0, 0);

    // 8) x2 = h + av @ wo   (fp32)
    gemm_tc<<<dim3(DD / 128, rows / 128, 1), 256, SM>>>(avHi, avLo, wotH, wotL, x2, nullptr, nullptr,
                                                        DD, DD, 0, 0, 0, 1.f, nullptr, h, 0, 0);

    // 9) h2 = ln2(x2) -> hi/lo
    ln_kernel<<<rows, 256>>>(x2, ln2_g, ln2_b, nullptr, h2Hi, h2Lo);

    // 10) ff = gelu(h2 @ w1 + b1) -> hi/lo
    gemm_tc<<<dim3(HH / 128, rows / 128, 1), 256, SM>>>(h2Hi, h2Lo, w1tH, w1tL, nullptr, ffHi, ffLo,
                                                        HH, DD, 0, 0, 0, 1.f, b1, nullptr, 0, 1);

    // 11) out = x2 + ff @ w2 + b2   (fp32)
    gemm_tc<<<dim3(DD / 128, rows / 128, 1), 256, SM>>>(ffHi, ffLo, w2tH, w2tL, out, nullptr, nullptr,
                                                        DD, HH, 0, 0, 0, 1.f, b2, x2, 0, 0);
}

// round 17
// speedup vs baseline: 2.6046x; 1.0026x over previous
#include <cuda_runtime.h>
#include <cuda_bf16.h>
#include <math.h>
#include <stdint.h>

constexpr int BB = 8, SS = 2048, DD = 1024, HH = 4096;

// ---------------- scratch ----------------------------------------------------
__device__ float g_h  [(size_t)BB*SS*DD];
__device__ float g_v  [(size_t)BB*SS*DD];
__device__ float g_s  [(size_t)BB*SS*SS];
__device__ float g_x2 [(size_t)BB*SS*DD];
__device__ __nv_bfloat16 g_h_hi [(size_t)BB*SS*DD],  g_h_lo [(size_t)BB*SS*DD];
__device__ __nv_bfloat16 g_q_hi [(size_t)BB*SS*DD],  g_q_lo [(size_t)BB*SS*DD];
__device__ __nv_bfloat16 g_k_hi [(size_t)BB*SS*DD],  g_k_lo [(size_t)BB*SS*DD];
__device__ __nv_bfloat16 g_vt_hi[(size_t)BB*SS*DD],  g_vt_lo[(size_t)BB*SS*DD];
__device__ __nv_bfloat16 g_s_hi [(size_t)BB*SS*SS],  g_s_lo [(size_t)BB*SS*SS];
__device__ __nv_bfloat16 g_av_hi[(size_t)BB*SS*DD],  g_av_lo[(size_t)BB*SS*DD];
__device__ __nv_bfloat16 g_h2_hi[(size_t)BB*SS*DD],  g_h2_lo[(size_t)BB*SS*DD];
__device__ __nv_bfloat16 g_ff_hi[(size_t)BB*SS*HH],  g_ff_lo[(size_t)BB*SS*HH];
__device__ __nv_bfloat16 g_wqt_hi[(size_t)DD*DD], g_wqt_lo[(size_t)DD*DD];
__device__ __nv_bfloat16 g_wkt_hi[(size_t)DD*DD], g_wkt_lo[(size_t)DD*DD];
__device__ __nv_bfloat16 g_wvt_hi[(size_t)DD*DD], g_wvt_lo[(size_t)DD*DD];
__device__ __nv_bfloat16 g_wot_hi[(size_t)DD*DD], g_wot_lo[(size_t)DD*DD];
__device__ __nv_bfloat16 g_w1t_hi[(size_t)DD*HH], g_w1t_lo[(size_t)DD*HH];
__device__ __nv_bfloat16 g_w2t_hi[(size_t)DD*HH], g_w2t_lo[(size_t)DD*HH];

// ---------------- helpers ----------------------------------------------------
__device__ __forceinline__ void hilo(float v, float& hf, float& lf) {
    __nv_bfloat16 h = __float2bfloat16(v);
    hf = __bfloat162float(h);
    lf = v - hf;
}
__device__ __forceinline__ uint32_t pack_bf2(float a, float b) {
    __nv_bfloat162 t = __floats2bfloat162_rn(a, b);
    return *reinterpret_cast<uint32_t*>(&t);
}
__device__ __forceinline__ uint32_t smem_u32(const void* p) {
    uint32_t a;
    asm("{ .reg .u64 t; cvta.to.shared.u64 t, %1; cvt.u32.u64 %0, t; }" : "=r"(a) : "l"(p));
    return a;
}
__device__ __forceinline__ void ldsm_x4(uint32_t* r, uint32_t addr) {
    asm volatile("ldmatrix.sync.aligned.m8n8.x4.shared.b16 {%0,%1,%2,%3}, [%4];"
                 : "=r"(r[0]), "=r"(r[1]), "=r"(r[2]), "=r"(r[3]) : "r"(addr));
}
__device__ __forceinline__ void ldsm_x2(uint32_t* r, uint32_t addr) {
    asm volatile("ldmatrix.sync.aligned.m8n8.x2.shared.b16 {%0,%1}, [%2];"
                 : "=r"(r[0]), "=r"(r[1]) : "r"(addr));
}
__device__ __forceinline__ void mma16816(float* d, const uint32_t* a, const uint32_t* b) {
    asm volatile("mma.sync.aligned.m16n8k16.row.col.f32.bf16.bf16.f32 "
                 "{%0,%1,%2,%3},{%4,%5,%6,%7},{%8,%9},{%0,%1,%2,%3};"
                 : "+f"(d[0]), "+f"(d[1]), "+f"(d[2]), "+f"(d[3])
                 : "r"(a[0]), "r"(a[1]), "r"(a[2]), "r"(a[3]), "r"(b[0]), "r"(b[1]));
}

// ---------------- block reductions -------------------------------------------
__device__ __forceinline__ float blockReduceSum(float v, float* shm) {
    int lane = threadIdx.x & 31, wid = threadIdx.x >> 5;
    #pragma unroll
    for (int o = 16; o; o >>= 1) v += __shfl_xor_sync(0xffffffffu, v, o);
    if (lane == 0) shm[wid] = v;
    __syncthreads();
    if (wid == 0) {
        float x = (lane < (blockDim.x >> 5)) ? shm[lane] : 0.f;
        #pragma unroll
        for (int o = 16; o; o >>= 1) x += __shfl_xor_sync(0xffffffffu, x, o);
        if (lane == 0) shm[0] = x;
    }
    __syncthreads();
    float r = shm[0]; __syncthreads(); return r;
}
__device__ __forceinline__ float blockReduceMax(float v, float* shm) {
    int lane = threadIdx.x & 31, wid = threadIdx.x >> 5;
    #pragma unroll
    for (int o = 16; o; o >>= 1) v = fmaxf(v, __shfl_xor_sync(0xffffffffu, v, o));
    if (lane == 0) shm[wid] = v;
    __syncthreads();
    if (wid == 0) {
        float x = (lane < (blockDim.x >> 5)) ? shm[lane] : -INFINITY;
        #pragma unroll
        for (int o = 16; o; o >>= 1) x = fmaxf(x, __shfl_xor_sync(0xffffffffu, x, o));
        if (lane == 0) shm[0] = x;
    }
    __syncthreads();
    float r = shm[0]; __syncthreads(); return r;
}

// ---------------- LayerNorm (fp32 + hi/lo outputs) ---------------------------
__global__ void __launch_bounds__(256) ln_kernel(
    const float* __restrict__ x, const float* __restrict__ g, const float* __restrict__ b,
    float* __restrict__ outF, __nv_bfloat16* __restrict__ outHi, __nv_bfloat16* __restrict__ outLo)
{
    __shared__ float shm[32];
    long long row = blockIdx.x;
    const float* px = x + row * DD;
    int t = threadIdx.x;
    float4 v = *reinterpret_cast<const float4*>(px + t * 4);
    float s  = v.x + v.y + v.z + v.w;
    float sq = v.x*v.x + v.y*v.y + v.z*v.z + v.w*v.w;
    float total  = blockReduceSum(s,  shm);
    float total2 = blockReduceSum(sq, shm);
    float mean = total * (1.0f / DD);
    float var  = total2 * (1.0f / DD) - mean * mean;
    float rstd = rsqrtf(var + 1e-5f);
    float4 gg = *reinterpret_cast<const float4*>(g + t * 4);
    float4 bb = *reinterpret_cast<const float4*>(b + t * 4);
    float4 o;
    o.x = (v.x - mean) * rstd * gg.x + bb.x;
    o.y = (v.y - mean) * rstd * gg.y + bb.y;
    o.z = (v.z - mean) * rstd * gg.z + bb.z;
    o.w = (v.w - mean) * rstd * gg.w + bb.w;
    long long off = row * DD + t * 4;
    if (outF) *reinterpret_cast<float4*>(outF + off) = o;
    float h0,h1,h2,h3,l0,l1,l2,l3;
    hilo(o.x,h0,l0); hilo(o.y,h1,l1); hilo(o.z,h2,l2); hilo(o.w,h3,l3);
    uint2 uh; uh.x = pack_bf2(h0,h1); uh.y = pack_bf2(h2,h3);
    uint2 ul; ul.x = pack_bf2(l0,l1); ul.y = pack_bf2(l2,l3);
    *reinterpret_cast<uint2*>(outHi + off) = uh;
    *reinterpret_cast<uint2*>(outLo + off) = ul;
}

// ---------------- Softmax (fp32 in, hi/lo out) -------------------------------
__global__ void __launch_bounds__(256) softmax_kernel(
    const float* __restrict__ s, __nv_bfloat16* __restrict__ oHi, __nv_bfloat16* __restrict__ oLo)
{
    __shared__ float shm[32];
    long long row = blockIdx.x;
    const float* p = s + row * SS;
    int t = threadIdx.x;
    float v[8];
    float mx = -INFINITY;
    #pragma unroll
    for (int i = 0; i < 8; i++) { v[i] = p[t + i * 256]; mx = fmaxf(mx, v[i]); }
    mx = blockReduceMax(mx, shm);
    float sum = 0.f;
    #pragma unroll
    for (int i = 0; i < 8; i++) { v[i] = expf(v[i] - mx); sum += v[i]; }
    sum = blockReduceSum(sum, shm);
    float inv = 1.0f / sum;
    #pragma unroll
    for (int i = 0; i < 8; i++) {
        float val = v[i] * inv, hf, lf;
        hilo(val, hf, lf);
        long long off = row * SS + t + i * 256;
        oHi[off] = __float2bfloat16(hf);
        oLo[off] = __float2bfloat16(lf);
    }
}

// ---------------- transpose-convert: in[R,C] fp32 -> out[C,R] hi/lo bf16 -----
__global__ void __launch_bounds__(256) transconv(
    const float* __restrict__ in, __nv_bfloat16* __restrict__ ohi, __nv_bfloat16* __restrict__ olo,
    int R, int C, long long sIn, long long sOut)
{
    __shared__ float t[32][33];
    const float* I = in + (long long)blockIdx.z * sIn;
    int c0 = blockIdx.x * 32, r0 = blockIdx.y * 32;
    int tx = threadIdx.x, ty = threadIdx.y;
    #pragma unroll
    for (int i = ty; i < 32; i += 8)
        t[i][tx] = I[(long long)(r0 + i) * C + c0 + tx];
    __syncthreads();
    long long ob = (long long)blockIdx.z * sOut;
    #pragma unroll
    for (int i = ty; i < 32; i += 8) {
        float v = t[tx][i];           // = in[r0+tx][c0+i]
        float hf, lf; hilo(v, hf, lf);
        long long off = ob + (long long)(c0 + i) * R + r0 + tx;
        ohi[off] = __float2bfloat16(hf);
        olo[off] = __float2bfloat16(lf);
    }
}

// ---------------- bf16x3 HMMA GEMM (mma.sync, sm_80 PTX path) ----------------
// C[M,N] = alpha * A[M,K] @ B[N,K]^T, A/B as bf16 hi/lo pairs.
// Tile 128x128, k-chunk 64, 8 warps (2x4), warp tile 64x32, 3 compensated passes.
constexpr int ROWB   = 144;               // 64 bf16 = 128B + 16B pad (conflict-free ldmatrix)
constexpr int TILEB  = 128 * ROWB;        // 18432 B per tile
constexpr int STAGEB = 4 * TILEB;         // Ahi, Alo, Bhi, Blo = 73728 B
constexpr int SMEMB  = 2 * STAGEB;        // 147456 B

__global__ void __launch_bounds__(256) gemm_tc(
    const __nv_bfloat16* __restrict__ Ahi, const __nv_bfloat16* __restrict__ Alo,
    const __nv_bfloat16* __restrict__ Bhi, const __nv_bfloat16* __restrict__ Blo,
    float* __restrict__ outF, __nv_bfloat16* __restrict__ outHi, __nv_bfloat16* __restrict__ outLo,
    int N, int K,
    long long sA, long long sB, long long sC,
    float alpha, const float* __restrict__ bias,
    const float* __restrict__ resid, long long sR, int act)
{
    extern __shared__ __align__(16) char smem[];
    uint32_t sb = smem_u32(smem);
    const int tid = threadIdx.x, wid = tid >> 5, lane = tid & 31;
    const long long bz = blockIdx.z;
    const int n0 = blockIdx.x << 7, m0 = blockIdx.y << 7;
    const int m0w = (wid >> 2) << 6;      // warp row offset (0 or 64)
    const int n0w = (wid & 3) << 5;       // warp col offset (0,32,64,96)

    const __nv_bfloat16* base[4];
    base[0] = Ahi + bz * sA + (long long)m0 * K;
    base[1] = Alo + bz * sA + (long long)m0 * K;
    base[2] = Bhi + bz * sB + (long long)n0 * K;
    base[3] = Blo + bz * sB + (long long)n0 * K;

    const int NC = K >> 6;

    // loader: 4 tiles x (128 rows x 8 segs of 16B); dest row stride 144B
    auto load_chunk = [&](uint32_t stg, int k0) {
        #pragma unroll
        for (int t4 = 0; t4 < 4; t4++) {
            const __nv_bfloat16* gb = base[t4] + k0;
            #pragma unroll
            for (int ii = 0; ii < 4; ii++) {
                int task = ii * 256 + tid;       // 0..1023
                int r = task >> 3, seg = task & 7;
                const __nv_bfloat16* g = gb + (long long)r * K + seg * 8;
                uint32_t d = stg + t4 * TILEB + r * ROWB + seg * 16;
                asm volatile("cp.async.cg.shared.global [%0], [%1], 16;" :: "r"(d), "l"(g) : "memory");
            }
        }
    };

    float acc[4][4][4];
    #pragma unroll
    for (int mt = 0; mt < 4; mt++)
        #pragma unroll
        for (int nt = 0; nt < 4; nt++)
            #pragma unroll
            for (int i = 0; i < 4; i++) acc[mt][nt][i] = 0.f;

    load_chunk(sb, 0);
    asm volatile("cp.async.commit_group;" ::: "memory");

    for (int c = 0; c < NC; c++) {
        if (c + 1 < NC) {
            load_chunk(sb + (((c + 1) & 1) ? STAGEB : 0), (c + 1) << 6);
            asm volatile("cp.async.commit_group;" ::: "memory");
            asm volatile("cp.async.wait_group 1;" ::: "memory");
        } else {
            asm volatile("cp.async.wait_group 0;" ::: "memory");
        }
        __syncthreads();

        const uint32_t stg = sb + ((c & 1) ? STAGEB : 0);
        const uint32_t aHiB = stg, aLoB = stg + TILEB, bHiB = stg + 2*TILEB, bLoB = stg + 3*TILEB;
        // per-lane ldmatrix address components
        const uint32_t aRow = (m0w + (lane & 15)) * ROWB + ((lane >> 4) << 3) * 2;
        const uint32_t bRow = (n0w + (lane & 7)) * ROWB + (((lane >> 3) & 1) << 3) * 2;

        #pragma unroll
        for (int ks = 0; ks < 4; ks++) {
            const uint32_t kOff = (ks << 4) * 2;   // ks*16 bf16 = 32B
            uint32_t ah[4][4], bh[4][2], bl[4][2];
            #pragma unroll
            for (int mt = 0; mt < 4; mt++) ldsm_x4(ah[mt], aHiB + aRow + (mt << 4) * ROWB + kOff);
            #pragma unroll
            for (int nt = 0; nt < 4; nt++) ldsm_x2(bh[nt], bHiB + bRow + (nt << 3) * ROWB + kOff);
            #pragma unroll
            for (int nt = 0; nt < 4; nt++) ldsm_x2(bl[nt], bLoB + bRow + (nt << 3) * ROWB + kOff);
            #pragma unroll
            for (int mt = 0; mt < 4; mt++)
                #pragma unroll
                for (int nt = 0; nt < 4; nt++) mma16816(acc[mt][nt], ah[mt], bh[nt]);
            #pragma unroll
            for (int mt = 0; mt < 4; mt++)
                #pragma unroll
                for (int nt = 0; nt < 4; nt++) mma16816(acc[mt][nt], ah[mt], bl[nt]);
            uint32_t al[4][4];
            #pragma unroll
            for (int mt = 0; mt < 4; mt++) ldsm_x4(al[mt], aLoB + aRow + (mt << 4) * ROWB + kOff);
            #pragma unroll
            for (int mt = 0; mt < 4; mt++)
                #pragma unroll
                for (int nt = 0; nt < 4; nt++) mma16816(acc[mt][nt], al[mt], bh[nt]);
        }
        __syncthreads();   // all warps done with this buffer before it is reloaded
    }

    // epilogue: acc -> smem [128][132] -> coalesced global with fused ops
    float* epi = reinterpret_cast<float*>(smem);
    #pragma unroll
    for (int mt = 0; mt < 4; mt++)
        #pragma unroll
        for (int nt = 0; nt < 4; nt++) {
            int r = m0w + (mt << 4) + (lane >> 2);
            int cc = n0w + (nt << 3) + ((lane & 3) << 1);
            epi[r * 132 + cc]           = acc[mt][nt][0];
            epi[r * 132 + cc + 1]       = acc[mt][nt][1];
            epi[(r + 8) * 132 + cc]     = acc[mt][nt][2];
            epi[(r + 8) * 132 + cc + 1] = acc[mt][nt][3];
        }
    __syncthreads();

    #pragma unroll
    for (int i = 0; i < 16; i++) {
        int f = i * 256 + tid;          // float4 index within 128x128 tile
        int mm = f >> 5, q4 = (f & 31) << 2;
        float4 v = *reinterpret_cast<float4*>(&epi[mm * 132 + q4]);
        v.x *= alpha; v.y *= alpha; v.z *= alpha; v.w *= alpha;
        if (bias) {
            float4 bb = *reinterpret_cast<const float4*>(bias + n0 + q4);
            v.x += bb.x; v.y += bb.y; v.z += bb.z; v.w += bb.w;
        }
        if (act == 1) {
            v.x = 0.5f * v.x * (1.0f + erff(v.x * 0.70710678118654752f));
            v.y = 0.5f * v.y * (1.0f + erff(v.y * 0.70710678118654752f));
            v.z = 0.5f * v.z * (1.0f + erff(v.z * 0.70710678118654752f));
            v.w = 0.5f * v.w * (1.0f + erff(v.w * 0.70710678118654752f));
        }
        long long goff = bz * sC + (long long)(m0 + mm) * N + n0 + q4;
        if (resid) {
            float4 rr = *reinterpret_cast<const float4*>(resid + bz * sR + (long long)(m0 + mm) * N + n0 + q4);
            v.x += rr.x; v.y += rr.y; v.z += rr.z; v.w += rr.w;
        }
        if (outF) *reinterpret_cast<float4*>(outF + goff) = v;
        if (outHi) {
            float h0,h1,h2,h3,l0,l1,l2,l3;
            hilo(v.x,h0,l0); hilo(v.y,h1,l1); hilo(v.z,h2,l2); hilo(v.w,h3,l3);
            uint2 uh; uh.x = pack_bf2(h0,h1); uh.y = pack_bf2(h2,h3);
            uint2 ul; ul.x = pack_bf2(l0,l1); ul.y = pack_bf2(l2,l3);
            *reinterpret_cast<uint2*>(outHi + goff) = uh;
            *reinterpret_cast<uint2*>(outLo + goff) = ul;
        }
    }
}

// ---------------- driver -----------------------------------------------------
template <typename T>
static inline T* sym(const void* s) {
    void* p = nullptr;
    cudaGetSymbolAddress(&p, s);
    return reinterpret_cast<T*>(p);
}

extern "C" void kernel_launch(void* const* d_in, const int* in_sizes, int n_in,
                              void* d_out, int out_size) {
    const float* x     = (const float*)d_in[0];
    const float* ln1_g = (const float*)d_in[1];
    const float* ln1_b = (const float*)d_in[2];
    const float* wq    = (const float*)d_in[3];
    const float* wk    = (const float*)d_in[4];
    const float* wv    = (const float*)d_in[5];
    const float* wo    = (const float*)d_in[6];
    const float* ln2_g = (const float*)d_in[7];
    const float* ln2_b = (const float*)d_in[8];
    const float* w1    = (const float*)d_in[9];
    const float* b1    = (const float*)d_in[10];
    const float* w2    = (const float*)d_in[11];
    const float* b2    = (const float*)d_in[12];
    float* out = (float*)d_out;

    float* h   = sym<float>(g_h);
    float* v   = sym<float>(g_v);
    float* s   = sym<float>(g_s);
    float* x2  = sym<float>(g_x2);
    __nv_bfloat16 *hHi = sym<__nv_bfloat16>(g_h_hi),  *hLo = sym<__nv_bfloat16>(g_h_lo);
    __nv_bfloat16 *qHi = sym<__nv_bfloat16>(g_q_hi),  *qLo = sym<__nv_bfloat16>(g_q_lo);
    __nv_bfloat16 *kHi = sym<__nv_bfloat16>(g_k_hi),  *kLo = sym<__nv_bfloat16>(g_k_lo);
    __nv_bfloat16 *vtHi= sym<__nv_bfloat16>(g_vt_hi), *vtLo= sym<__nv_bfloat16>(g_vt_lo);
    __nv_bfloat16 *sHi = sym<__nv_bfloat16>(g_s_hi),  *sLo = sym<__nv_bfloat16>(g_s_lo);
    __nv_bfloat16 *avHi= sym<__nv_bfloat16>(g_av_hi), *avLo= sym<__nv_bfloat16>(g_av_lo);
    __nv_bfloat16 *h2Hi= sym<__nv_bfloat16>(g_h2_hi), *h2Lo= sym<__nv_bfloat16>(g_h2_lo);
    __nv_bfloat16 *ffHi= sym<__nv_bfloat16>(g_ff_hi), *ffLo= sym<__nv_bfloat16>(g_ff_lo);
    __nv_bfloat16 *wqtH= sym<__nv_bfloat16>(g_wqt_hi),*wqtL= sym<__nv_bfloat16>(g_wqt_lo);
    __nv_bfloat16 *wktH= sym<__nv_bfloat16>(g_wkt_hi),*wktL= sym<__nv_bfloat16>(g_wkt_lo);
    __nv_bfloat16 *wvtH= sym<__nv_bfloat16>(g_wvt_hi),*wvtL= sym<__nv_bfloat16>(g_wvt_lo);
    __nv_bfloat16 *wotH= sym<__nv_bfloat16>(g_wot_hi),*wotL= sym<__nv_bfloat16>(g_wot_lo);
    __nv_bfloat16 *w1tH= sym<__nv_bfloat16>(g_w1t_hi),*w1tL= sym<__nv_bfloat16>(g_w1t_lo);
    __nv_bfloat16 *w2tH= sym<__nv_bfloat16>(g_w2t_hi),*w2tL= sym<__nv_bfloat16>(g_w2t_lo);

    cudaFuncSetAttribute(gemm_tc, cudaFuncAttributeMaxDynamicSharedMemorySize, SMEMB);
    const int SM = SMEMB;
    const int rows = BB * SS;
    const float scale = 1.0f / sqrtf((float)DD);
    const long long SD = (long long)SS * DD, SSq = (long long)SS * SS;

    // Launch order arranged so launch #6 (ncu -s 5 -c 1) is a gemm_tc.
    // 1) h = ln1(x): fp32 + hi/lo
    ln_kernel<<<rows, 256>>>(x, ln1_g, ln1_b, h, hHi, hLo);

    // 2-5) qkv/wo weight transposes -> [N,K] hi/lo  (launches 2..5)
    {
        dim3 b(32, 8);
        transconv<<<dim3(32, 32, 1), b>>>(wq, wqtH, wqtL, DD, DD, 0, 0);
        transconv<<<dim3(32, 32, 1), b>>>(wk, wktH, wktL, DD, DD, 0, 0);
        transconv<<<dim3(32, 32, 1), b>>>(wv, wvtH, wvtL, DD, DD, 0, 0);
        transconv<<<dim3(32, 32, 1), b>>>(wo, wotH, wotL, DD, DD, 0, 0);
    }

    // 6-8) q,k (hi/lo out), v (fp32 out)   — launch #6 is gemm_tc (profiled)
    {
        dim3 grid(DD / 128, rows / 128, 1);
        gemm_tc<<<grid, 256, SM>>>(hHi, hLo, wqtH, wqtL, nullptr, qHi, qLo, DD, DD, 0, 0, 0, 1.f, nullptr, nullptr, 0, 0);
        gemm_tc<<<grid, 256, SM>>>(hHi, hLo, wktH, wktL, nullptr, kHi, kLo, DD, DD, 0, 0, 0, 1.f, nullptr, nullptr, 0, 0);
        gemm_tc<<<grid, 256, SM>>>(hHi, hLo, wvtH, wvtL, v, nullptr, nullptr, DD, DD, 0, 0, 0, 1.f, nullptr, nullptr, 0, 0);
    }

    // 9) v^T per batch -> [D,S] hi/lo
    transconv<<<dim3(DD / 32, SS / 32, BB), dim3(32, 8)>>>(v, vtHi, vtLo, SS, DD, SD, SD);

    // 10) s = scale * q @ k^T   (batched)
    gemm_tc<<<dim3(SS / 128, SS / 128, BB), 256, SM>>>(qHi, qLo, kHi, kLo, s, nullptr, nullptr,
                                                       SS, DD, SD, SD, SSq, scale, nullptr, nullptr, 0, 0);

    // 11) softmax -> hi/lo
    softmax_kernel<<<rows, 256>>>(s, sHi, sLo);

    // 12) av = a @ v   (B = v^T [D,S], batched)
    gemm_tc<<<dim3(DD / 128, SS / 128, BB), 256, SM>>>(sHi, sLo, vtHi, vtLo, nullptr, avHi, avLo,
                                                       DD, SS, SSq, SD, SD, 1.f, nullptr, nullptr, 0, 0);

    // 13) x2 = h + av @ wo   (fp32)
    gemm_tc<<<dim3(DD / 128, rows / 128, 1), 256, SM>>>(avHi, avLo, wotH, wotL, x2, nullptr, nullptr,
                                                        DD, DD, 0, 0, 0, 1.f, nullptr, h, 0, 0);

    // 14) h2 = ln2(x2) -> hi/lo
    ln_kernel<<<rows, 256>>>(x2, ln2_g, ln2_b, nullptr, h2Hi, h2Lo);

    // 15-16) deferred MLP weight transposes (still before their consumers)
    {
        dim3 b(32, 8);
        transconv<<<dim3(128, 32, 1), b>>>(w1, w1tH, w1tL, DD, HH, 0, 0);  // [1024,4096] -> [4096,1024]
        transconv<<<dim3(32, 128, 1), b>>>(w2, w2tH, w2tL, HH, DD, 0, 0);  // [4096,1024] -> [1024,4096]
    }

    // 17) ff = gelu(h2 @ w1 + b1) -> hi/lo
    gemm_tc<<<dim3(HH / 128, rows / 128, 1), 256, SM>>>(h2Hi, h2Lo, w1tH, w1tL, nullptr, ffHi, ffLo,
                                                        HH, DD, 0, 0, 0, 1.f, b1, nullptr, 0, 1);

    // 18) out = x2 + ff @ w2 + b2   (fp32)
    gemm_tc<<<dim3(DD / 128, rows / 128, 1), 256, SM>>>(ffHi, ffLo, w2tH, w2tL, out, nullptr, nullptr,
                                                        DD, HH, 0, 0, 0, 1.f, b2, x2, 0, 0);
}